// round 1
// baseline (speedup 1.0000x reference)
#include <cuda_runtime.h>
#include <math.h>

// Problem dims
#define Bdim 64
#define Qdim 256
#define Adim 256
#define Ddim 256
#define Kdim 16

#define QT 64            // q rows per CTA

// Shared memory layout (in floats)
#define T_PITCH 257
#define QS_PITCH 33
#define DAS_PITCH 257
#define T_OFF   0
#define S1_OFF  (64 * T_PITCH)                 // 16448
#define WS_OFF  (S1_OFF + 64 * QS_PITCH)       // Qs: 64x33 = 2112 floats
#define DAS_OFF S1_OFF                          // stage2 reuses stage1 region
#define VQ_OFF  (S1_OFF + (64*QS_PITCH + 32*256))  // 16448 + 10304 = 26752
#define VD_OFF  (VQ_OFF + 64)
#define SMEM_FLOATS (VD_OFF + 256)              // 27072 floats = 108288 B

__global__ void __launch_bounds__(256, 2)
ntn_kernel(const float* __restrict__ q_em,
           const float* __restrict__ da_em,
           const float* __restrict__ w,
           const float* __restrict__ V,
           const float* __restrict__ bias,
           float* __restrict__ out)
{
    extern __shared__ float sm[];
    const int t  = threadIdx.x;
    const int bx = blockIdx.x;
    const int qt = bx & 3;
    const int k  = (bx >> 2) & 15;
    const int b  = bx >> 6;
    const int q0 = qt * QT;

    const int tx = t & 15;   // a / e group
    const int ty = t >> 4;   // q group

    float* T   = sm + T_OFF;
    float* Qs  = sm + S1_OFF;
    float* Ws  = sm + WS_OFF;
    float* DAs = sm + DAS_OFF;
    float* vq  = sm + VQ_OFF;
    float* vd  = sm + VD_OFF;

    // ---------------- mid vectors: vq[64], vd[256] ----------------
    {
        // vq[q] = Vq[k] . q_em[b, q0+q, :]  -- 4 threads per q row
        int q = t >> 2, part = t & 3;
        const float4* vk = (const float4*)(V + (size_t)k * 512 + part * 64);
        const float4* qr = (const float4*)(q_em + ((size_t)b * Qdim + q0 + q) * Ddim + part * 64);
        float s0 = 0.f, s1 = 0.f, s2 = 0.f, s3 = 0.f;
        #pragma unroll
        for (int i = 0; i < 16; i += 4) {
            float4 a0 = vk[i+0], b0 = qr[i+0];
            float4 a1 = vk[i+1], b1 = qr[i+1];
            float4 a2 = vk[i+2], b2 = qr[i+2];
            float4 a3 = vk[i+3], b3 = qr[i+3];
            s0 += a0.x*b0.x + a0.y*b0.y + a0.z*b0.z + a0.w*b0.w;
            s1 += a1.x*b1.x + a1.y*b1.y + a1.z*b1.z + a1.w*b1.w;
            s2 += a2.x*b2.x + a2.y*b2.y + a2.z*b2.z + a2.w*b2.w;
            s3 += a3.x*b3.x + a3.y*b3.y + a3.z*b3.z + a3.w*b3.w;
        }
        float s = (s0 + s1) + (s2 + s3);
        s += __shfl_xor_sync(0xffffffffu, s, 1);
        s += __shfl_xor_sync(0xffffffffu, s, 2);
        if (part == 0) vq[q] = s;
    }
    {
        // vd[a] = Vd[k] . da_em[b, a, :]  -- 1 thread per a row
        const float4* vk = (const float4*)(V + (size_t)k * 512 + 256);
        const float4* dr = (const float4*)(da_em + ((size_t)b * Adim + t) * Ddim);
        float s0 = 0.f, s1 = 0.f, s2 = 0.f, s3 = 0.f;
        #pragma unroll 4
        for (int i = 0; i < 64; i += 4) {
            float4 a0 = vk[i+0], b0 = dr[i+0];
            float4 a1 = vk[i+1], b1 = dr[i+1];
            float4 a2 = vk[i+2], b2 = dr[i+2];
            float4 a3 = vk[i+3], b3 = dr[i+3];
            s0 += a0.x*b0.x + a0.y*b0.y + a0.z*b0.z + a0.w*b0.w;
            s1 += a1.x*b1.x + a1.y*b1.y + a1.z*b1.z + a1.w*b1.w;
            s2 += a2.x*b2.x + a2.y*b2.y + a2.z*b2.z + a2.w*b2.w;
            s3 += a3.x*b3.x + a3.y*b3.y + a3.z*b3.z + a3.w*b3.w;
        }
        vd[t] = (s0 + s1) + (s2 + s3);
    }

    // ---------------- Stage 1: T[64][256] = Q_b[q0:q0+64,:] @ W_k ----------------
    float acc[4][16];
    #pragma unroll
    for (int i = 0; i < 4; i++)
        #pragma unroll
        for (int j = 0; j < 16; j++) acc[i][j] = 0.f;

    const float* qbase = q_em + ((size_t)b * Qdim + q0) * Ddim;
    const float* wbase = w + (size_t)k * Ddim * Ddim;

    for (int d0 = 0; d0 < Ddim; d0 += 32) {
        // Load Qs[64][32] (padded pitch 33)
        #pragma unroll
        for (int i = 0; i < 2; i++) {
            int lin4 = i * 256 + t;
            int row  = lin4 >> 3;
            int col4 = lin4 & 7;
            float4 v4 = *(const float4*)(qbase + (size_t)row * Ddim + d0 + col4 * 4);
            float* dst = Qs + row * QS_PITCH + col4 * 4;
            dst[0] = v4.x; dst[1] = v4.y; dst[2] = v4.z; dst[3] = v4.w;
        }
        // Load Ws[32][256] (contiguous block of w)
        {
            const float4* wg  = (const float4*)(wbase + (size_t)d0 * Ddim);
            float4*       ws4 = (float4*)Ws;
            #pragma unroll
            for (int i = 0; i < 8; i++) ws4[i * 256 + t] = wg[i * 256 + t];
        }
        __syncthreads();

        #pragma unroll 4
        for (int dd = 0; dd < 32; dd++) {
            float qr[4], wr[16];
            #pragma unroll
            for (int i = 0; i < 4; i++) qr[i] = Qs[(ty * 4 + i) * QS_PITCH + dd];
            #pragma unroll
            for (int j = 0; j < 16; j++) wr[j] = Ws[dd * 256 + tx + 16 * j];
            #pragma unroll
            for (int i = 0; i < 4; i++)
                #pragma unroll
                for (int j = 0; j < 16; j++)
                    acc[i][j] += qr[i] * wr[j];
        }
        __syncthreads();
    }

    // Write T (padded pitch 257)
    #pragma unroll
    for (int i = 0; i < 4; i++)
        #pragma unroll
        for (int j = 0; j < 16; j++)
            T[(ty * 4 + i) * T_PITCH + tx + 16 * j] = acc[i][j];
    __syncthreads();

    // ---------------- Stage 2: out_tile = T @ DA_b^T ----------------
    #pragma unroll
    for (int i = 0; i < 4; i++)
        #pragma unroll
        for (int j = 0; j < 16; j++) acc[i][j] = 0.f;

    const float* dabase = da_em + (size_t)b * Adim * Ddim;

    for (int e0 = 0; e0 < Ddim; e0 += 32) {
        // Load DAs transposed: DAs[ee][a], ee in [0,32), a in [0,256)
        #pragma unroll
        for (int i = 0; i < 8; i++) {
            int lin4 = i * 256 + t;
            int a    = lin4 >> 3;
            int ee4  = lin4 & 7;
            float4 v4 = *(const float4*)(dabase + (size_t)a * Ddim + e0 + ee4 * 4);
            DAs[(ee4 * 4 + 0) * DAS_PITCH + a] = v4.x;
            DAs[(ee4 * 4 + 1) * DAS_PITCH + a] = v4.y;
            DAs[(ee4 * 4 + 2) * DAS_PITCH + a] = v4.z;
            DAs[(ee4 * 4 + 3) * DAS_PITCH + a] = v4.w;
        }
        __syncthreads();

        #pragma unroll 4
        for (int ee = 0; ee < 32; ee++) {
            float qr[4], wr[16];
            #pragma unroll
            for (int i = 0; i < 4; i++) qr[i] = T[(ty * 4 + i) * T_PITCH + e0 + ee];
            #pragma unroll
            for (int j = 0; j < 16; j++) wr[j] = DAs[ee * DAS_PITCH + tx + 16 * j];
            #pragma unroll
            for (int i = 0; i < 4; i++)
                #pragma unroll
                for (int j = 0; j < 16; j++)
                    acc[i][j] += qr[i] * wr[j];
        }
        __syncthreads();
    }

    // ---------------- Epilogue: + vq + vd + bias, sigmoid, store ----------------
    const float bk = bias[k];
    float vqr[4];
    #pragma unroll
    for (int i = 0; i < 4; i++) vqr[i] = vq[ty * 4 + i];
    float vdr[16];
    #pragma unroll
    for (int j = 0; j < 16; j++) vdr[j] = vd[tx + 16 * j];

    float* obase = out + (((size_t)b * Kdim + k) * Qdim + q0) * (size_t)Adim;
    #pragma unroll
    for (int i = 0; i < 4; i++) {
        float* orow = obase + (size_t)(ty * 4 + i) * Adim;
        #pragma unroll
        for (int j = 0; j < 16; j++) {
            float x = acc[i][j] + vqr[i] + vdr[j] + bk;
            orow[tx + 16 * j] = 1.0f / (1.0f + __expf(-x));
        }
    }
}

extern "C" void kernel_launch(void* const* d_in, const int* in_sizes, int n_in,
                              void* d_out, int out_size)
{
    (void)in_sizes; (void)n_in; (void)out_size;
    const float* q_em  = (const float*)d_in[0];
    const float* da_em = (const float*)d_in[1];
    const float* w     = (const float*)d_in[2];
    const float* V     = (const float*)d_in[3];
    const float* bias  = (const float*)d_in[4];
    float* out = (float*)d_out;

    size_t smem = (size_t)SMEM_FLOATS * sizeof(float);
    cudaFuncSetAttribute(ntn_kernel, cudaFuncAttributeMaxDynamicSharedMemorySize, (int)smem);

    dim3 grid(Bdim * Kdim * (Qdim / QT));  // 4096
    ntn_kernel<<<grid, 256, smem>>>(q_em, da_em, w, V, bias, out);
}

// round 2
// speedup vs baseline: 1.0012x; 1.0012x over previous
#include <cuda_runtime.h>
#include <math.h>

// Problem dims
#define Bdim 64
#define Qdim 256
#define Adim 256
#define Ddim 256
#define Kdim 16

#define QT 64            // q rows per CTA

// Shared memory layout (in floats)
#define T_PITCH 257
#define QS_PITCH 33
#define DAS_PITCH 257
#define T_OFF   0
#define S1_OFF  (64 * T_PITCH)                 // 16448
#define WS_OFF  (S1_OFF + 64 * QS_PITCH)       // Qs: 64x33 = 2112 floats
#define DAS_OFF S1_OFF                          // stage2 reuses stage1 region
#define VQ_OFF  (S1_OFF + (64*QS_PITCH + 32*256))  // 16448 + 10304 = 26752
#define VD_OFF  (VQ_OFF + 64)
#define SMEM_FLOATS (VD_OFF + 256)              // 27072 floats = 108288 B

__global__ void __launch_bounds__(256, 2)
ntn_kernel(const float* __restrict__ q_em,
           const float* __restrict__ da_em,
           const float* __restrict__ w,
           const float* __restrict__ V,
           const float* __restrict__ bias,
           float* __restrict__ out)
{
    extern __shared__ float sm[];
    const int t  = threadIdx.x;
    const int bx = blockIdx.x;
    const int qt = bx & 3;
    const int k  = (bx >> 2) & 15;
    const int b  = bx >> 6;
    const int q0 = qt * QT;

    const int tx = t & 15;   // a / e group
    const int ty = t >> 4;   // q group

    float* T   = sm + T_OFF;
    float* Qs  = sm + S1_OFF;
    float* Ws  = sm + WS_OFF;
    float* DAs = sm + DAS_OFF;
    float* vq  = sm + VQ_OFF;
    float* vd  = sm + VD_OFF;

    // ---------------- mid vectors: vq[64], vd[256] ----------------
    {
        // vq[q] = Vq[k] . q_em[b, q0+q, :]  -- 4 threads per q row
        int q = t >> 2, part = t & 3;
        const float4* vk = (const float4*)(V + (size_t)k * 512 + part * 64);
        const float4* qr = (const float4*)(q_em + ((size_t)b * Qdim + q0 + q) * Ddim + part * 64);
        float s0 = 0.f, s1 = 0.f, s2 = 0.f, s3 = 0.f;
        #pragma unroll
        for (int i = 0; i < 16; i += 4) {
            float4 a0 = vk[i+0], b0 = qr[i+0];
            float4 a1 = vk[i+1], b1 = qr[i+1];
            float4 a2 = vk[i+2], b2 = qr[i+2];
            float4 a3 = vk[i+3], b3 = qr[i+3];
            s0 += a0.x*b0.x + a0.y*b0.y + a0.z*b0.z + a0.w*b0.w;
            s1 += a1.x*b1.x + a1.y*b1.y + a1.z*b1.z + a1.w*b1.w;
            s2 += a2.x*b2.x + a2.y*b2.y + a2.z*b2.z + a2.w*b2.w;
            s3 += a3.x*b3.x + a3.y*b3.y + a3.z*b3.z + a3.w*b3.w;
        }
        float s = (s0 + s1) + (s2 + s3);
        s += __shfl_xor_sync(0xffffffffu, s, 1);
        s += __shfl_xor_sync(0xffffffffu, s, 2);
        if (part == 0) vq[q] = s;
    }
    {
        // vd[a] = Vd[k] . da_em[b, a, :]  -- 1 thread per a row
        const float4* vk = (const float4*)(V + (size_t)k * 512 + 256);
        const float4* dr = (const float4*)(da_em + ((size_t)b * Adim + t) * Ddim);
        float s0 = 0.f, s1 = 0.f, s2 = 0.f, s3 = 0.f;
        #pragma unroll 4
        for (int i = 0; i < 64; i += 4) {
            float4 a0 = vk[i+0], b0 = dr[i+0];
            float4 a1 = vk[i+1], b1 = dr[i+1];
            float4 a2 = vk[i+2], b2 = dr[i+2];
            float4 a3 = vk[i+3], b3 = dr[i+3];
            s0 += a0.x*b0.x + a0.y*b0.y + a0.z*b0.z + a0.w*b0.w;
            s1 += a1.x*b1.x + a1.y*b1.y + a1.z*b1.z + a1.w*b1.w;
            s2 += a2.x*b2.x + a2.y*b2.y + a2.z*b2.z + a2.w*b2.w;
            s3 += a3.x*b3.x + a3.y*b3.y + a3.z*b3.z + a3.w*b3.w;
        }
        vd[t] = (s0 + s1) + (s2 + s3);
    }

    // ---------------- Stage 1: T[64][256] = Q_b[q0:q0+64,:] @ W_k ----------------
    float acc[4][16];
    #pragma unroll
    for (int i = 0; i < 4; i++)
        #pragma unroll
        for (int j = 0; j < 16; j++) acc[i][j] = 0.f;

    const float* qbase = q_em + ((size_t)b * Qdim + q0) * Ddim;
    const float* wbase = w + (size_t)k * Ddim * Ddim;

    for (int d0 = 0; d0 < Ddim; d0 += 32) {
        // Load Qs[64][32] (padded pitch 33)
        #pragma unroll
        for (int i = 0; i < 2; i++) {
            int lin4 = i * 256 + t;
            int row  = lin4 >> 3;
            int col4 = lin4 & 7;
            float4 v4 = *(const float4*)(qbase + (size_t)row * Ddim + d0 + col4 * 4);
            float* dst = Qs + row * QS_PITCH + col4 * 4;
            dst[0] = v4.x; dst[1] = v4.y; dst[2] = v4.z; dst[3] = v4.w;
        }
        // Load Ws[32][256] (contiguous block of w)
        {
            const float4* wg  = (const float4*)(wbase + (size_t)d0 * Ddim);
            float4*       ws4 = (float4*)Ws;
            #pragma unroll
            for (int i = 0; i < 8; i++) ws4[i * 256 + t] = wg[i * 256 + t];
        }
        __syncthreads();

        #pragma unroll 4
        for (int dd = 0; dd < 32; dd++) {
            float qr[4], wr[16];
            #pragma unroll
            for (int i = 0; i < 4; i++) qr[i] = Qs[(ty * 4 + i) * QS_PITCH + dd];
            #pragma unroll
            for (int j = 0; j < 16; j++) wr[j] = Ws[dd * 256 + tx + 16 * j];
            #pragma unroll
            for (int i = 0; i < 4; i++)
                #pragma unroll
                for (int j = 0; j < 16; j++)
                    acc[i][j] += qr[i] * wr[j];
        }
        __syncthreads();
    }

    // Write T (padded pitch 257)
    #pragma unroll
    for (int i = 0; i < 4; i++)
        #pragma unroll
        for (int j = 0; j < 16; j++)
            T[(ty * 4 + i) * T_PITCH + tx + 16 * j] = acc[i][j];
    __syncthreads();

    // ---------------- Stage 2: out_tile = T @ DA_b^T ----------------
    #pragma unroll
    for (int i = 0; i < 4; i++)
        #pragma unroll
        for (int j = 0; j < 16; j++) acc[i][j] = 0.f;

    const float* dabase = da_em + (size_t)b * Adim * Ddim;

    for (int e0 = 0; e0 < Ddim; e0 += 32) {
        // Load DAs transposed: DAs[ee][a], ee in [0,32), a in [0,256)
        #pragma unroll
        for (int i = 0; i < 8; i++) {
            int lin4 = i * 256 + t;
            int a    = lin4 >> 3;
            int ee4  = lin4 & 7;
            float4 v4 = *(const float4*)(dabase + (size_t)a * Ddim + e0 + ee4 * 4);
            DAs[(ee4 * 4 + 0) * DAS_PITCH + a] = v4.x;
            DAs[(ee4 * 4 + 1) * DAS_PITCH + a] = v4.y;
            DAs[(ee4 * 4 + 2) * DAS_PITCH + a] = v4.z;
            DAs[(ee4 * 4 + 3) * DAS_PITCH + a] = v4.w;
        }
        __syncthreads();

        #pragma unroll 4
        for (int ee = 0; ee < 32; ee++) {
            float qr[4], wr[16];
            #pragma unroll
            for (int i = 0; i < 4; i++) qr[i] = T[(ty * 4 + i) * T_PITCH + e0 + ee];
            #pragma unroll
            for (int j = 0; j < 16; j++) wr[j] = DAs[ee * DAS_PITCH + tx + 16 * j];
            #pragma unroll
            for (int i = 0; i < 4; i++)
                #pragma unroll
                for (int j = 0; j < 16; j++)
                    acc[i][j] += qr[i] * wr[j];
        }
        __syncthreads();
    }

    // ---------------- Epilogue: + vq + vd + bias, sigmoid, store ----------------
    const float bk = bias[k];
    float vqr[4];
    #pragma unroll
    for (int i = 0; i < 4; i++) vqr[i] = vq[ty * 4 + i];
    float vdr[16];
    #pragma unroll
    for (int j = 0; j < 16; j++) vdr[j] = vd[tx + 16 * j];

    float* obase = out + (((size_t)b * Kdim + k) * Qdim + q0) * (size_t)Adim;
    #pragma unroll
    for (int i = 0; i < 4; i++) {
        float* orow = obase + (size_t)(ty * 4 + i) * Adim;
        #pragma unroll
        for (int j = 0; j < 16; j++) {
            float x = acc[i][j] + vqr[i] + vdr[j] + bk;
            orow[tx + 16 * j] = 1.0f / (1.0f + __expf(-x));
        }
    }
}

extern "C" void kernel_launch(void* const* d_in, const int* in_sizes, int n_in,
                              void* d_out, int out_size)
{
    (void)in_sizes; (void)n_in; (void)out_size;
    const float* q_em  = (const float*)d_in[0];
    const float* da_em = (const float*)d_in[1];
    const float* w     = (const float*)d_in[2];
    const float* V     = (const float*)d_in[3];
    const float* bias  = (const float*)d_in[4];
    float* out = (float*)d_out;

    size_t smem = (size_t)SMEM_FLOATS * sizeof(float);
    cudaFuncSetAttribute(ntn_kernel, cudaFuncAttributeMaxDynamicSharedMemorySize, (int)smem);

    dim3 grid(Bdim * Kdim * (Qdim / QT));  // 4096
    ntn_kernel<<<grid, 256, smem>>>(q_em, da_em, w, V, bias, out);
}

// round 3
// speedup vs baseline: 1.7828x; 1.7806x over previous
#include <cuda_runtime.h>
#include <cuda_bf16.h>
#include <math.h>

#define Bdim 64
#define Qdim 256
#define Adim 256
#define Ddim 256
#define Kdim 16
#define QT 64

// Pitches in bf16 halves (odd multiples of 16B-units -> conflict-free ldmatrix)
#define QP 24     // Qs / DAs pitch (16 data + 8 pad)
#define WP 264    // Ws / Ts pitch (256 data + 8 pad)

// SMEM byte offsets
#define TS_H_OFF  0
#define TS_L_OFF  33792                 // 64*264*2
#define REG2_OFF  67584
#define QS_H_OFF  REG2_OFF
#define QS_L_OFF  (REG2_OFF + 3072)     // 64*24*2
#define WS_H_OFF  (REG2_OFF + 6144)
#define WS_L_OFF  (REG2_OFF + 14592)    // +16*264*2
#define DAS_H_OFF REG2_OFF
#define DAS_L_OFF (REG2_OFF + 12288)    // 256*24*2
#define VQ_OFF    (REG2_OFF + 24576)
#define VD_OFF    (VQ_OFF + 256)
#define SMEM_BYTES (VD_OFF + 1024)      // 93440 B

__device__ __forceinline__ void ldsm_x4(unsigned* r, const void* p) {
    unsigned addr = (unsigned)__cvta_generic_to_shared(p);
    asm volatile("ldmatrix.sync.aligned.m8n8.x4.shared.b16 {%0,%1,%2,%3}, [%4];"
                 : "=r"(r[0]), "=r"(r[1]), "=r"(r[2]), "=r"(r[3]) : "r"(addr));
}
__device__ __forceinline__ void ldsm_x4t(unsigned* r, const void* p) {
    unsigned addr = (unsigned)__cvta_generic_to_shared(p);
    asm volatile("ldmatrix.sync.aligned.m8n8.x4.trans.shared.b16 {%0,%1,%2,%3}, [%4];"
                 : "=r"(r[0]), "=r"(r[1]), "=r"(r[2]), "=r"(r[3]) : "r"(addr));
}
__device__ __forceinline__ void mma_bf16(float* c, const unsigned* a, unsigned b0, unsigned b1) {
    asm volatile("mma.sync.aligned.m16n8k16.row.col.f32.bf16.bf16.f32 "
                 "{%0,%1,%2,%3}, {%4,%5,%6,%7}, {%8,%9}, {%0,%1,%2,%3};"
                 : "+f"(c[0]), "+f"(c[1]), "+f"(c[2]), "+f"(c[3])
                 : "r"(a[0]), "r"(a[1]), "r"(a[2]), "r"(a[3]), "r"(b0), "r"(b1));
}
__device__ __forceinline__ void cvt2(float x, __nv_bfloat16& h, __nv_bfloat16& l) {
    h = __float2bfloat16(x);
    l = __float2bfloat16(x - __bfloat162float(h));
}
__device__ __forceinline__ void cvt_store4(float4 v, __nv_bfloat16* ph, __nv_bfloat16* pl) {
    __nv_bfloat16 h0, h1, h2, h3, l0, l1, l2, l3;
    cvt2(v.x, h0, l0); cvt2(v.y, h1, l1); cvt2(v.z, h2, l2); cvt2(v.w, h3, l3);
    *(__nv_bfloat162*)(ph + 0) = __nv_bfloat162(h0, h1);
    *(__nv_bfloat162*)(ph + 2) = __nv_bfloat162(h2, h3);
    *(__nv_bfloat162*)(pl + 0) = __nv_bfloat162(l0, l1);
    *(__nv_bfloat162*)(pl + 2) = __nv_bfloat162(l2, l3);
}
__device__ __forceinline__ float sigf(float x) { return 1.0f / (1.0f + __expf(-x)); }

__global__ void __launch_bounds__(256)
ntn_mma_kernel(const float* __restrict__ q_em,
               const float* __restrict__ da_em,
               const float* __restrict__ w,
               const float* __restrict__ V,
               const float* __restrict__ bias,
               float* __restrict__ out)
{
    extern __shared__ char sm[];
    __nv_bfloat16* Ts_h  = (__nv_bfloat16*)(sm + TS_H_OFF);
    __nv_bfloat16* Ts_l  = (__nv_bfloat16*)(sm + TS_L_OFF);
    __nv_bfloat16* Qs_h  = (__nv_bfloat16*)(sm + QS_H_OFF);
    __nv_bfloat16* Qs_l  = (__nv_bfloat16*)(sm + QS_L_OFF);
    __nv_bfloat16* Ws_h  = (__nv_bfloat16*)(sm + WS_H_OFF);
    __nv_bfloat16* Ws_l  = (__nv_bfloat16*)(sm + WS_L_OFF);
    __nv_bfloat16* DAs_h = (__nv_bfloat16*)(sm + DAS_H_OFF);
    __nv_bfloat16* DAs_l = (__nv_bfloat16*)(sm + DAS_L_OFF);
    float* vq = (float*)(sm + VQ_OFF);
    float* vd = (float*)(sm + VD_OFF);

    const int t  = threadIdx.x;
    const int bx = blockIdx.x;
    const int qt = bx & 3;
    const int k  = (bx >> 2) & 15;
    const int b  = bx >> 6;
    const int q0 = qt * QT;

    const int warp = t >> 5;
    const int lane = t & 31;
    const int wq   = warp >> 1;   // q group (0..3) -> 16 rows
    const int we   = warp & 1;    // e/a half (0..1) -> 128 cols
    const int q0w  = wq * 16;
    const int grp  = lane >> 2;
    const int tig  = lane & 3;

    // ---------------- mid vectors: vq[64], vd[256] (fp32, exact) ----------------
    {
        int q = t >> 2, part = t & 3;
        const float4* vk = (const float4*)(V + (size_t)k * 512 + part * 64);
        const float4* qr = (const float4*)(q_em + ((size_t)b * Qdim + q0 + q) * Ddim + part * 64);
        float s0 = 0.f, s1 = 0.f, s2 = 0.f, s3 = 0.f;
        #pragma unroll
        for (int i = 0; i < 16; i += 4) {
            float4 a0 = vk[i+0], b0 = qr[i+0];
            float4 a1 = vk[i+1], b1 = qr[i+1];
            float4 a2 = vk[i+2], b2 = qr[i+2];
            float4 a3 = vk[i+3], b3 = qr[i+3];
            s0 += a0.x*b0.x + a0.y*b0.y + a0.z*b0.z + a0.w*b0.w;
            s1 += a1.x*b1.x + a1.y*b1.y + a1.z*b1.z + a1.w*b1.w;
            s2 += a2.x*b2.x + a2.y*b2.y + a2.z*b2.z + a2.w*b2.w;
            s3 += a3.x*b3.x + a3.y*b3.y + a3.z*b3.z + a3.w*b3.w;
        }
        float s = (s0 + s1) + (s2 + s3);
        s += __shfl_xor_sync(0xffffffffu, s, 1);
        s += __shfl_xor_sync(0xffffffffu, s, 2);
        if (part == 0) vq[q] = s;
    }
    {
        const float4* vk = (const float4*)(V + (size_t)k * 512 + 256);
        const float4* dr = (const float4*)(da_em + ((size_t)b * Adim + t) * Ddim);
        float s0 = 0.f, s1 = 0.f, s2 = 0.f, s3 = 0.f;
        #pragma unroll 4
        for (int i = 0; i < 64; i += 4) {
            float4 a0 = vk[i+0], b0 = dr[i+0];
            float4 a1 = vk[i+1], b1 = dr[i+1];
            float4 a2 = vk[i+2], b2 = dr[i+2];
            float4 a3 = vk[i+3], b3 = dr[i+3];
            s0 += a0.x*b0.x + a0.y*b0.y + a0.z*b0.z + a0.w*b0.w;
            s1 += a1.x*b1.x + a1.y*b1.y + a1.z*b1.z + a1.w*b1.w;
            s2 += a2.x*b2.x + a2.y*b2.y + a2.z*b2.z + a2.w*b2.w;
            s3 += a3.x*b3.x + a3.y*b3.y + a3.z*b3.z + a3.w*b3.w;
        }
        vd[t] = (s0 + s1) + (s2 + s3);
    }

    float acc[16][4];
    #pragma unroll
    for (int j = 0; j < 16; j++) { acc[j][0]=0.f; acc[j][1]=0.f; acc[j][2]=0.f; acc[j][3]=0.f; }

    const float* qbase  = q_em + ((size_t)b * Qdim + q0) * Ddim;
    const float* wbase  = w + (size_t)k * Ddim * Ddim;
    const float* dabase = da_em + (size_t)b * Adim * Ddim;

    // ldmatrix address components
    const int a_row = q0w + (lane & 15);
    const int a_csel = (lane >> 4) * 8;
    const int bw_row = lane & 15;            // stage1 B (trans): d row
    const int bw_csel = (lane >> 4) * 8;
    const int bd_aoff = ((lane >> 4) & 1) * 8 + (lane & 7);  // stage2 B
    const int bd_col  = (lane & 8) ? 8 : 0;

    // =============== Stage 1: T[64][256] = Q @ W_k  (bf16x3) ===============
    const int qrow = t >> 2, qc4 = t & 3;
    float4 qreg, wreg[4];
    qreg = *(const float4*)(qbase + (size_t)qrow * Ddim + qc4 * 4);
    #pragma unroll
    for (int i = 0; i < 4; i++) {
        int lin = i * 256 + t, row = lin >> 6, c4 = lin & 63;
        wreg[i] = *(const float4*)(wbase + (size_t)row * Ddim + c4 * 4);
    }

    for (int d0 = 0; d0 < Ddim; d0 += 16) {
        // commit staged registers to SMEM
        cvt_store4(qreg, Qs_h + qrow * QP + qc4 * 4, Qs_l + qrow * QP + qc4 * 4);
        #pragma unroll
        for (int i = 0; i < 4; i++) {
            int lin = i * 256 + t, row = lin >> 6, c4 = lin & 63;
            cvt_store4(wreg[i], Ws_h + row * WP + c4 * 4, Ws_l + row * WP + c4 * 4);
        }
        __syncthreads();

        // prefetch next k-step
        if (d0 + 16 < Ddim) {
            qreg = *(const float4*)(qbase + (size_t)qrow * Ddim + (d0 + 16) + qc4 * 4);
            #pragma unroll
            for (int i = 0; i < 4; i++) {
                int lin = i * 256 + t, row = lin >> 6, c4 = lin & 63;
                wreg[i] = *(const float4*)(wbase + (size_t)(d0 + 16 + row) * Ddim + c4 * 4);
            }
        }

        unsigned ah[4], al[4];
        ldsm_x4(ah, Qs_h + a_row * QP + a_csel);
        ldsm_x4(al, Qs_l + a_row * QP + a_csel);

        #pragma unroll
        for (int n2 = 0; n2 < 8; n2++) {
            int eoff = bw_row * WP + we * 128 + n2 * 16 + bw_csel;
            unsigned bh[4], bl[4];
            ldsm_x4t(bh, Ws_h + eoff);
            ldsm_x4t(bl, Ws_l + eoff);
            float* c0 = acc[2 * n2];
            float* c1 = acc[2 * n2 + 1];
            mma_bf16(c0, ah, bh[0], bh[1]);
            mma_bf16(c0, ah, bl[0], bl[1]);
            mma_bf16(c0, al, bh[0], bh[1]);
            mma_bf16(c1, ah, bh[2], bh[3]);
            mma_bf16(c1, ah, bl[2], bl[3]);
            mma_bf16(c1, al, bh[2], bh[3]);
        }
        __syncthreads();
    }

    // -------- write T to SMEM as bf16 hi/lo --------
    #pragma unroll
    for (int j = 0; j < 16; j++) {
        int col = we * 128 + j * 8 + tig * 2;
        int r0  = q0w + grp;
        __nv_bfloat16 h0, l0, h1, l1, h2, l2, h3, l3;
        cvt2(acc[j][0], h0, l0); cvt2(acc[j][1], h1, l1);
        cvt2(acc[j][2], h2, l2); cvt2(acc[j][3], h3, l3);
        *(__nv_bfloat162*)&Ts_h[r0 * WP + col]       = __nv_bfloat162(h0, h1);
        *(__nv_bfloat162*)&Ts_l[r0 * WP + col]       = __nv_bfloat162(l0, l1);
        *(__nv_bfloat162*)&Ts_h[(r0 + 8) * WP + col] = __nv_bfloat162(h2, h3);
        *(__nv_bfloat162*)&Ts_l[(r0 + 8) * WP + col] = __nv_bfloat162(l2, l3);
    }
    __syncthreads();

    // =============== Stage 2: OUT = T @ DA^T (bf16x3) ===============
    #pragma unroll
    for (int j = 0; j < 16; j++) { acc[j][0]=0.f; acc[j][1]=0.f; acc[j][2]=0.f; acc[j][3]=0.f; }

    float4 dreg[4];
    #pragma unroll
    for (int i = 0; i < 4; i++) {
        int lin = i * 256 + t, row = lin >> 2, c4 = lin & 3;
        dreg[i] = *(const float4*)(dabase + (size_t)row * Ddim + c4 * 4);
    }

    for (int e0 = 0; e0 < Ddim; e0 += 16) {
        #pragma unroll
        for (int i = 0; i < 4; i++) {
            int lin = i * 256 + t, row = lin >> 2, c4 = lin & 3;
            cvt_store4(dreg[i], DAs_h + row * QP + c4 * 4, DAs_l + row * QP + c4 * 4);
        }
        __syncthreads();

        if (e0 + 16 < Ddim) {
            #pragma unroll
            for (int i = 0; i < 4; i++) {
                int lin = i * 256 + t, row = lin >> 2, c4 = lin & 3;
                dreg[i] = *(const float4*)(dabase + (size_t)row * Ddim + (e0 + 16) + c4 * 4);
            }
        }

        unsigned ah[4], al[4];
        ldsm_x4(ah, Ts_h + a_row * WP + e0 + a_csel);
        ldsm_x4(al, Ts_l + a_row * WP + e0 + a_csel);

        #pragma unroll
        for (int n2 = 0; n2 < 8; n2++) {
            int aoff = (we * 128 + n2 * 16 + bd_aoff) * QP + bd_col;
            unsigned bh[4], bl[4];
            ldsm_x4(bh, DAs_h + aoff);
            ldsm_x4(bl, DAs_l + aoff);
            float* c0 = acc[2 * n2];
            float* c1 = acc[2 * n2 + 1];
            mma_bf16(c0, ah, bh[0], bh[1]);
            mma_bf16(c0, ah, bl[0], bl[1]);
            mma_bf16(c0, al, bh[0], bh[1]);
            mma_bf16(c1, ah, bh[2], bh[3]);
            mma_bf16(c1, ah, bl[2], bl[3]);
            mma_bf16(c1, al, bh[2], bh[3]);
        }
        __syncthreads();
    }

    // =============== Epilogue: + vq + vd + bias, sigmoid ===============
    const float bk = bias[k];
    float* ob = out + (((size_t)b * Kdim + k) * Qdim + q0) * (size_t)Adim;
    #pragma unroll
    for (int j = 0; j < 16; j++) {
        int col = we * 128 + j * 8 + tig * 2;
        int r0  = q0w + grp;
        float vd0 = vd[col], vd1 = vd[col + 1];
        float vq0 = vq[r0],  vq1 = vq[r0 + 8];
        float2 o0, o1;
        o0.x = sigf(acc[j][0] + vq0 + vd0 + bk);
        o0.y = sigf(acc[j][1] + vq0 + vd1 + bk);
        o1.x = sigf(acc[j][2] + vq1 + vd0 + bk);
        o1.y = sigf(acc[j][3] + vq1 + vd1 + bk);
        *(float2*)&ob[(size_t)r0 * Adim + col]       = o0;
        *(float2*)&ob[(size_t)(r0 + 8) * Adim + col] = o1;
    }
}

extern "C" void kernel_launch(void* const* d_in, const int* in_sizes, int n_in,
                              void* d_out, int out_size)
{
    (void)in_sizes; (void)n_in; (void)out_size;
    const float* q_em  = (const float*)d_in[0];
    const float* da_em = (const float*)d_in[1];
    const float* w     = (const float*)d_in[2];
    const float* V     = (const float*)d_in[3];
    const float* bias  = (const float*)d_in[4];
    float* out = (float*)d_out;

    cudaFuncSetAttribute(ntn_mma_kernel, cudaFuncAttributeMaxDynamicSharedMemorySize, SMEM_BYTES);
    dim3 grid(Bdim * Kdim * (Qdim / QT));  // 4096
    ntn_mma_kernel<<<grid, 256, SMEM_BYTES>>>(q_em, da_em, w, V, bias, out);
}

// round 4
// speedup vs baseline: 1.7839x; 1.0006x over previous
#include <cuda_runtime.h>
#include <cuda_bf16.h>
#include <math.h>

#define Bdim 64
#define Qdim 256
#define Adim 256
#define Ddim 256
#define Kdim 16
#define QT 64

// Pitches in bf16 halves (odd multiples of 16B-units -> conflict-free ldmatrix)
#define QP 24     // Qs / DAs pitch (16 data + 8 pad)
#define WP 264    // Ws / Ts pitch (256 data + 8 pad)

// SMEM byte offsets
#define TS_H_OFF 0
#define TS_L_OFF 33792                   // 64*264*2
#define IB_OFF   67584                   // input double-buffer region
#define BUF_STRIDE 24576
// stage-1 buffer internal offsets
#define QS_H 0
#define QS_L 3072                        // 64*24*2
#define WS_H 6144
#define WS_L 14592                       // +16*264*2
// stage-2 buffer internal offsets
#define DA_H 0
#define DA_L 12288                       // 256*24*2
#define VQ_OFF (IB_OFF + 2*BUF_STRIDE)   // 116736
#define VD_OFF (VQ_OFF + 256)
#define SMEM_BYTES (VD_OFF + 1024)       // 118016

__device__ __forceinline__ void ldsm_x4(unsigned* r, const void* p) {
    unsigned addr = (unsigned)__cvta_generic_to_shared(p);
    asm volatile("ldmatrix.sync.aligned.m8n8.x4.shared.b16 {%0,%1,%2,%3}, [%4];"
                 : "=r"(r[0]), "=r"(r[1]), "=r"(r[2]), "=r"(r[3]) : "r"(addr));
}
__device__ __forceinline__ void ldsm_x4t(unsigned* r, const void* p) {
    unsigned addr = (unsigned)__cvta_generic_to_shared(p);
    asm volatile("ldmatrix.sync.aligned.m8n8.x4.trans.shared.b16 {%0,%1,%2,%3}, [%4];"
                 : "=r"(r[0]), "=r"(r[1]), "=r"(r[2]), "=r"(r[3]) : "r"(addr));
}
__device__ __forceinline__ void mma_bf16(float* c, const unsigned* a, unsigned b0, unsigned b1) {
    asm volatile("mma.sync.aligned.m16n8k16.row.col.f32.bf16.bf16.f32 "
                 "{%0,%1,%2,%3}, {%4,%5,%6,%7}, {%8,%9}, {%0,%1,%2,%3};"
                 : "+f"(c[0]), "+f"(c[1]), "+f"(c[2]), "+f"(c[3])
                 : "r"(a[0]), "r"(a[1]), "r"(a[2]), "r"(a[3]), "r"(b0), "r"(b1));
}
__device__ __forceinline__ void cvt2(float x, __nv_bfloat16& h, __nv_bfloat16& l) {
    h = __float2bfloat16(x);
    l = __float2bfloat16(x - __bfloat162float(h));
}
__device__ __forceinline__ void cvt_store4(float4 v, __nv_bfloat16* ph, __nv_bfloat16* pl) {
    __nv_bfloat16 h0, h1, h2, h3, l0, l1, l2, l3;
    cvt2(v.x, h0, l0); cvt2(v.y, h1, l1); cvt2(v.z, h2, l2); cvt2(v.w, h3, l3);
    *(__nv_bfloat162*)(ph + 0) = __nv_bfloat162(h0, h1);
    *(__nv_bfloat162*)(ph + 2) = __nv_bfloat162(h2, h3);
    *(__nv_bfloat162*)(pl + 0) = __nv_bfloat162(l0, l1);
    *(__nv_bfloat162*)(pl + 2) = __nv_bfloat162(l2, l3);
}
__device__ __forceinline__ float sigf(float x) { return 1.0f / (1.0f + __expf(-x)); }

__global__ void __launch_bounds__(256)
ntn_mma_kernel(const float* __restrict__ q_em,
               const float* __restrict__ da_em,
               const float* __restrict__ w,
               const float* __restrict__ V,
               const float* __restrict__ bias,
               float* __restrict__ out)
{
    extern __shared__ char sm[];
    __nv_bfloat16* Ts_h = (__nv_bfloat16*)(sm + TS_H_OFF);
    __nv_bfloat16* Ts_l = (__nv_bfloat16*)(sm + TS_L_OFF);
    float* vq = (float*)(sm + VQ_OFF);
    float* vd = (float*)(sm + VD_OFF);

    const int t  = threadIdx.x;
    const int bx = blockIdx.x;
    const int qt = bx & 3;
    const int k  = (bx >> 2) & 15;
    const int b  = bx >> 6;
    const int q0 = qt * QT;

    const int warp = t >> 5;
    const int lane = t & 31;
    const int wq   = warp >> 2;   // 0..1: 32 q-rows each
    const int we   = warp & 3;    // 0..3: 64 cols each
    const int grp  = lane >> 2;
    const int tig  = lane & 3;

    // ---------------- mid vectors: vq[64], vd[256] (fp32, exact) ----------------
    {
        int q = t >> 2, part = t & 3;
        const float4* vk = (const float4*)(V + (size_t)k * 512 + part * 64);
        const float4* qr = (const float4*)(q_em + ((size_t)b * Qdim + q0 + q) * Ddim + part * 64);
        float s0 = 0.f, s1 = 0.f, s2 = 0.f, s3 = 0.f;
        #pragma unroll
        for (int i = 0; i < 16; i += 4) {
            float4 a0 = vk[i+0], b0 = qr[i+0];
            float4 a1 = vk[i+1], b1 = qr[i+1];
            float4 a2 = vk[i+2], b2 = qr[i+2];
            float4 a3 = vk[i+3], b3 = qr[i+3];
            s0 += a0.x*b0.x + a0.y*b0.y + a0.z*b0.z + a0.w*b0.w;
            s1 += a1.x*b1.x + a1.y*b1.y + a1.z*b1.z + a1.w*b1.w;
            s2 += a2.x*b2.x + a2.y*b2.y + a2.z*b2.z + a2.w*b2.w;
            s3 += a3.x*b3.x + a3.y*b3.y + a3.z*b3.z + a3.w*b3.w;
        }
        float s = (s0 + s1) + (s2 + s3);
        s += __shfl_xor_sync(0xffffffffu, s, 1);
        s += __shfl_xor_sync(0xffffffffu, s, 2);
        if (part == 0) vq[q] = s;
    }
    {
        const float4* vk = (const float4*)(V + (size_t)k * 512 + 256);
        const float4* dr = (const float4*)(da_em + ((size_t)b * Adim + t) * Ddim);
        float s0 = 0.f, s1 = 0.f, s2 = 0.f, s3 = 0.f;
        #pragma unroll 4
        for (int i = 0; i < 64; i += 4) {
            float4 a0 = vk[i+0], b0 = dr[i+0];
            float4 a1 = vk[i+1], b1 = dr[i+1];
            float4 a2 = vk[i+2], b2 = dr[i+2];
            float4 a3 = vk[i+3], b3 = dr[i+3];
            s0 += a0.x*b0.x + a0.y*b0.y + a0.z*b0.z + a0.w*b0.w;
            s1 += a1.x*b1.x + a1.y*b1.y + a1.z*b1.z + a1.w*b1.w;
            s2 += a2.x*b2.x + a2.y*b2.y + a2.z*b2.z + a2.w*b2.w;
            s3 += a3.x*b3.x + a3.y*b3.y + a3.z*b3.z + a3.w*b3.w;
        }
        vd[t] = (s0 + s1) + (s2 + s3);
    }

    float acc[2][8][4];
    #pragma unroll
    for (int m = 0; m < 2; m++)
        #pragma unroll
        for (int j = 0; j < 8; j++)
            #pragma unroll
            for (int c = 0; c < 4; c++) acc[m][j][c] = 0.f;

    const float* qbase  = q_em + ((size_t)b * Qdim + q0) * Ddim;
    const float* wbase  = w + (size_t)k * Ddim * Ddim;
    const float* dabase = da_em + (size_t)b * Adim * Ddim;

    // ldmatrix address components
    const int a_row  = wq * 32 + (lane & 15);
    const int a_csel = (lane >> 4) * 8;
    const int bw_row = lane & 15;                            // stage1 B (trans): d row
    const int bd_aoff = ((lane >> 4) & 1) * 8 + (lane & 7);  // stage2 B
    const int bd_col  = (lane & 8) ? 8 : 0;

    // =============== Stage 1: T[64][256] = Q @ W_k  (bf16x3, double-buffered) ===============
    const int qrow = t >> 2, qc4 = t & 3;
    float4 qreg, wreg[4];

    // prologue: load + store buffer 0
    qreg = *(const float4*)(qbase + (size_t)qrow * Ddim + qc4 * 4);
    #pragma unroll
    for (int i = 0; i < 4; i++) {
        int lin = i * 256 + t, row = lin >> 6, c4 = lin & 63;
        wreg[i] = *(const float4*)(wbase + (size_t)row * Ddim + c4 * 4);
    }
    {
        char* buf = sm + IB_OFF;
        cvt_store4(qreg, (__nv_bfloat16*)(buf + QS_H) + qrow * QP + qc4 * 4,
                         (__nv_bfloat16*)(buf + QS_L) + qrow * QP + qc4 * 4);
        #pragma unroll
        for (int i = 0; i < 4; i++) {
            int lin = i * 256 + t, row = lin >> 6, c4 = lin & 63;
            cvt_store4(wreg[i], (__nv_bfloat16*)(buf + WS_H) + row * WP + c4 * 4,
                                (__nv_bfloat16*)(buf + WS_L) + row * WP + c4 * 4);
        }
    }

    #pragma unroll 1
    for (int it = 0; it < 16; it++) {
        __syncthreads();
        const int d0 = it * 16;
        // prefetch next k-slab from GMEM
        if (it + 1 < 16) {
            qreg = *(const float4*)(qbase + (size_t)qrow * Ddim + (d0 + 16) + qc4 * 4);
            #pragma unroll
            for (int i = 0; i < 4; i++) {
                int lin = i * 256 + t, row = lin >> 6, c4 = lin & 63;
                wreg[i] = *(const float4*)(wbase + (size_t)(d0 + 16 + row) * Ddim + c4 * 4);
            }
        }
        char* cur = sm + IB_OFF + (it & 1) * BUF_STRIDE;
        __nv_bfloat16* Qs_h = (__nv_bfloat16*)(cur + QS_H);
        __nv_bfloat16* Qs_l = (__nv_bfloat16*)(cur + QS_L);
        __nv_bfloat16* Ws_h = (__nv_bfloat16*)(cur + WS_H);
        __nv_bfloat16* Ws_l = (__nv_bfloat16*)(cur + WS_L);

        unsigned ah[2][4], al[2][4];
        ldsm_x4(ah[0], Qs_h + a_row * QP + a_csel);
        ldsm_x4(ah[1], Qs_h + (a_row + 16) * QP + a_csel);
        ldsm_x4(al[0], Qs_l + a_row * QP + a_csel);
        ldsm_x4(al[1], Qs_l + (a_row + 16) * QP + a_csel);

        #pragma unroll
        for (int n2 = 0; n2 < 4; n2++) {
            int eoff = bw_row * WP + we * 64 + n2 * 16 + a_csel;
            unsigned bh[4], bl[4];
            ldsm_x4t(bh, Ws_h + eoff);
            ldsm_x4t(bl, Ws_l + eoff);
            #pragma unroll
            for (int m = 0; m < 2; m++) {
                float* c0 = acc[m][2 * n2];
                float* c1 = acc[m][2 * n2 + 1];
                mma_bf16(c0, ah[m], bh[0], bh[1]);
                mma_bf16(c0, ah[m], bl[0], bl[1]);
                mma_bf16(c0, al[m], bh[0], bh[1]);
                mma_bf16(c1, ah[m], bh[2], bh[3]);
                mma_bf16(c1, ah[m], bl[2], bl[3]);
                mma_bf16(c1, al[m], bh[2], bh[3]);
            }
        }
        // store prefetched slab into alternate buffer
        if (it + 1 < 16) {
            char* nxt = sm + IB_OFF + ((it + 1) & 1) * BUF_STRIDE;
            cvt_store4(qreg, (__nv_bfloat16*)(nxt + QS_H) + qrow * QP + qc4 * 4,
                             (__nv_bfloat16*)(nxt + QS_L) + qrow * QP + qc4 * 4);
            #pragma unroll
            for (int i = 0; i < 4; i++) {
                int lin = i * 256 + t, row = lin >> 6, c4 = lin & 63;
                cvt_store4(wreg[i], (__nv_bfloat16*)(nxt + WS_H) + row * WP + c4 * 4,
                                    (__nv_bfloat16*)(nxt + WS_L) + row * WP + c4 * 4);
            }
        }
    }

    // -------- write T to SMEM as bf16 hi/lo --------
    #pragma unroll
    for (int m = 0; m < 2; m++) {
        int r0 = wq * 32 + m * 16 + grp;
        #pragma unroll
        for (int j = 0; j < 8; j++) {
            int col = we * 64 + j * 8 + tig * 2;
            __nv_bfloat16 h0, l0, h1, l1, h2, l2, h3, l3;
            cvt2(acc[m][j][0], h0, l0); cvt2(acc[m][j][1], h1, l1);
            cvt2(acc[m][j][2], h2, l2); cvt2(acc[m][j][3], h3, l3);
            *(__nv_bfloat162*)&Ts_h[r0 * WP + col]       = __nv_bfloat162(h0, h1);
            *(__nv_bfloat162*)&Ts_l[r0 * WP + col]       = __nv_bfloat162(l0, l1);
            *(__nv_bfloat162*)&Ts_h[(r0 + 8) * WP + col] = __nv_bfloat162(h2, h3);
            *(__nv_bfloat162*)&Ts_l[(r0 + 8) * WP + col] = __nv_bfloat162(l2, l3);
        }
    }

    // =============== Stage 2: OUT = T @ DA^T (bf16x3, double-buffered) ===============
    #pragma unroll
    for (int m = 0; m < 2; m++)
        #pragma unroll
        for (int j = 0; j < 8; j++)
            #pragma unroll
            for (int c = 0; c < 4; c++) acc[m][j][c] = 0.f;

    float4 dreg[4];
    #pragma unroll
    for (int i = 0; i < 4; i++) {
        int lin = i * 256 + t, row = lin >> 2, c4 = lin & 3;
        dreg[i] = *(const float4*)(dabase + (size_t)row * Ddim + c4 * 4);
    }
    __syncthreads();   // Ts visible; stage-1 buffer reads complete before reuse
    {
        char* buf = sm + IB_OFF;
        #pragma unroll
        for (int i = 0; i < 4; i++) {
            int lin = i * 256 + t, row = lin >> 2, c4 = lin & 3;
            cvt_store4(dreg[i], (__nv_bfloat16*)(buf + DA_H) + row * QP + c4 * 4,
                                (__nv_bfloat16*)(buf + DA_L) + row * QP + c4 * 4);
        }
    }

    #pragma unroll 1
    for (int it = 0; it < 16; it++) {
        __syncthreads();
        const int e0 = it * 16;
        if (it + 1 < 16) {
            #pragma unroll
            for (int i = 0; i < 4; i++) {
                int lin = i * 256 + t, row = lin >> 2, c4 = lin & 3;
                dreg[i] = *(const float4*)(dabase + (size_t)row * Ddim + (e0 + 16) + c4 * 4);
            }
        }
        char* cur = sm + IB_OFF + (it & 1) * BUF_STRIDE;
        __nv_bfloat16* DAs_h = (__nv_bfloat16*)(cur + DA_H);
        __nv_bfloat16* DAs_l = (__nv_bfloat16*)(cur + DA_L);

        unsigned ah[2][4], al[2][4];
        ldsm_x4(ah[0], Ts_h + a_row * WP + e0 + a_csel);
        ldsm_x4(ah[1], Ts_h + (a_row + 16) * WP + e0 + a_csel);
        ldsm_x4(al[0], Ts_l + a_row * WP + e0 + a_csel);
        ldsm_x4(al[1], Ts_l + (a_row + 16) * WP + e0 + a_csel);

        #pragma unroll
        for (int n2 = 0; n2 < 4; n2++) {
            int aoff = (we * 64 + n2 * 16 + bd_aoff) * QP + bd_col;
            unsigned bh[4], bl[4];
            ldsm_x4(bh, DAs_h + aoff);
            ldsm_x4(bl, DAs_l + aoff);
            #pragma unroll
            for (int m = 0; m < 2; m++) {
                float* c0 = acc[m][2 * n2];
                float* c1 = acc[m][2 * n2 + 1];
                mma_bf16(c0, ah[m], bh[0], bh[1]);
                mma_bf16(c0, ah[m], bl[0], bl[1]);
                mma_bf16(c0, al[m], bh[0], bh[1]);
                mma_bf16(c1, ah[m], bh[2], bh[3]);
                mma_bf16(c1, ah[m], bl[2], bl[3]);
                mma_bf16(c1, al[m], bh[2], bh[3]);
            }
        }
        if (it + 1 < 16) {
            char* nxt = sm + IB_OFF + ((it + 1) & 1) * BUF_STRIDE;
            #pragma unroll
            for (int i = 0; i < 4; i++) {
                int lin = i * 256 + t, row = lin >> 2, c4 = lin & 3;
                cvt_store4(dreg[i], (__nv_bfloat16*)(nxt + DA_H) + row * QP + c4 * 4,
                                    (__nv_bfloat16*)(nxt + DA_L) + row * QP + c4 * 4);
            }
        }
    }

    // =============== Epilogue: + vq + vd + bias, sigmoid ===============
    const float bk = bias[k];
    float* ob = out + (((size_t)b * Kdim + k) * Qdim + q0) * (size_t)Adim;
    #pragma unroll
    for (int m = 0; m < 2; m++) {
        int r0 = wq * 32 + m * 16 + grp;
        float vq0 = vq[r0], vq1 = vq[r0 + 8];
        #pragma unroll
        for (int j = 0; j < 8; j++) {
            int col = we * 64 + j * 8 + tig * 2;
            float vd0 = vd[col], vd1 = vd[col + 1];
            float2 o0, o1;
            o0.x = sigf(acc[m][j][0] + vq0 + vd0 + bk);
            o0.y = sigf(acc[m][j][1] + vq0 + vd1 + bk);
            o1.x = sigf(acc[m][j][2] + vq1 + vd0 + bk);
            o1.y = sigf(acc[m][j][3] + vq1 + vd1 + bk);
            *(float2*)&ob[(size_t)r0 * Adim + col]       = o0;
            *(float2*)&ob[(size_t)(r0 + 8) * Adim + col] = o1;
        }
    }
}

extern "C" void kernel_launch(void* const* d_in, const int* in_sizes, int n_in,
                              void* d_out, int out_size)
{
    (void)in_sizes; (void)n_in; (void)out_size;
    const float* q_em  = (const float*)d_in[0];
    const float* da_em = (const float*)d_in[1];
    const float* w     = (const float*)d_in[2];
    const float* V     = (const float*)d_in[3];
    const float* bias  = (const float*)d_in[4];
    float* out = (float*)d_out;

    cudaFuncSetAttribute(ntn_mma_kernel, cudaFuncAttributeMaxDynamicSharedMemorySize, SMEM_BYTES);
    dim3 grid(Bdim * Kdim * (Qdim / QT));  // 4096
    ntn_mma_kernel<<<grid, 256, SMEM_BYTES>>>(q_em, da_em, w, V, bias, out);
}